// round 1
// baseline (speedup 1.0000x reference)
#include <cuda_runtime.h>

#define FULLMASK 0xffffffffu
#define NTAGS 32
#define BOS_IDX 30
#define EOS_IDX 31

static __device__ __forceinline__ unsigned long long pack2(float x, float y) {
    unsigned long long r;
    asm("mov.b64 %0, {%1,%2};" : "=l"(r) : "f"(x), "f"(y));
    return r;
}
static __device__ __forceinline__ void ffma2(unsigned long long& d,
                                             unsigned long long a,
                                             unsigned long long b) {
    asm("fma.rn.f32x2 %0, %1, %2, %0;" : "+l"(d) : "l"(a), "l"(b));
}
static __device__ __forceinline__ void unpack2(unsigned long long v, float& x, float& y) {
    asm("mov.b64 {%0,%1}, %2;" : "=f"(x), "=f"(y) : "l"(v));
}

// One warp per sequence. Lane j owns alpha[j] and E-row j (E = exp(transitions)).
// Per step: beta_i = exp(alpha_i - m) staged in smem, s_j = sum_i E[j,i]*beta_i
// via packed f32x2 FMAs, alpha'_j = e_t[j] + m + log(s_j).
__global__ __launch_bounds__(64) void crf_forward_kernel(
    const float* __restrict__ emission,   // [B, T, 32]
    const float* __restrict__ trans,      // [32, 32]
    float* __restrict__ out,              // [B]
    int B, int T)
{
    const int lane = threadIdx.x & 31;
    const int w    = threadIdx.x >> 5;
    const int b    = blockIdx.x * 2 + w;

    __shared__ float sbeta[2][2][NTAGS];  // [warp][double-buffer][tag]

    if (b >= B) return;  // warp-uniform

    // ---- one-time: E row for this lane, packed into f32x2 pairs ----
    unsigned long long er[16];
    {
        const float* trow = trans + lane * NTAGS;
        #pragma unroll
        for (int q = 0; q < 16; q++) {
            float a = expf(trow[2 * q]);       // exp(-1000) -> 0 for BOS row
            float c = expf(trow[2 * q + 1]);
            er[q] = pack2(a, c);
        }
    }

    const float* em = emission + (size_t)b * T * NTAGS + lane;

    // ---- step 0 (analytic: only BOS survives the init alpha) ----
    float alpha = em[0] + trans[lane * NTAGS + BOS_IDX];

    // ---- emission prefetch ring, depth 4 ----
    float e0 = em[(size_t)(1 < T ? 1 : T - 1) * NTAGS];
    float e1 = em[(size_t)(2 < T ? 2 : T - 1) * NTAGS];
    float e2 = em[(size_t)(3 < T ? 3 : T - 1) * NTAGS];
    float e3 = em[(size_t)(4 < T ? 4 : T - 1) * NTAGS];

    #pragma unroll 4
    for (int t = 1; t < T; ++t) {
        float e = e0;
        e0 = e1; e1 = e2; e2 = e3;
        int tp = (t + 4 < T) ? (t + 4) : (T - 1);
        e3 = em[(size_t)tp * NTAGS];

        // shift = alpha[EOS] (always finite, tracks the max within ~12)
        float m = __shfl_sync(FULLMASK, alpha, EOS_IDX);
        float beta = __expf(alpha - m);       // exp(-inf) = 0 for dead BOS lane

        float* sb = sbeta[w][t & 1];
        sb[lane] = beta;
        __syncwarp();

        unsigned long long sA = 0ull, sB = 0ull;
        const float4* bp = (const float4*)sb;
        #pragma unroll
        for (int q = 0; q < 8; q++) {
            float4 b4 = bp[q];
            ffma2(sA, er[2 * q],     pack2(b4.x, b4.y));
            ffma2(sB, er[2 * q + 1], pack2(b4.z, b4.w));
        }
        float ax, ay, bx, by;
        unpack2(sA, ax, ay);
        unpack2(sB, bx, by);
        float s = (ax + ay) + (bx + by);

        alpha = e + m + __logf(s);            // log(0) = -inf for BOS lane: stable
    }

    // ---- terminal: lse(alpha + trans[EOS, :]) over the warp ----
    float v = alpha + trans[EOS_IDX * NTAGS + lane];
    float mm = v;
    #pragma unroll
    for (int o = 16; o; o >>= 1)
        mm = fmaxf(mm, __shfl_xor_sync(FULLMASK, mm, o));
    float ex = __expf(v - mm);
    #pragma unroll
    for (int o = 16; o; o >>= 1)
        ex += __shfl_xor_sync(FULLMASK, ex, o);
    if (lane == 0)
        out[b] = mm + __logf(ex);
}

extern "C" void kernel_launch(void* const* d_in, const int* in_sizes, int n_in,
                              void* d_out, int out_size)
{
    // metadata order: emission [B,T,32] fp32, transitions [32,32] fp32.
    // Defensive: detect by size in case order differs.
    const float* em = (const float*)d_in[0];
    const float* tr = (const float*)d_in[1];
    long long em_elems = in_sizes[0];
    if (n_in >= 2 && in_sizes[0] == NTAGS * NTAGS && in_sizes[1] > NTAGS * NTAGS) {
        em = (const float*)d_in[1];
        tr = (const float*)d_in[0];
        em_elems = in_sizes[1];
    }

    int B = out_size;
    int T = (int)(em_elems / ((long long)B * NTAGS));

    int blocks = (B + 1) / 2;  // 2 warps (2 sequences) per 64-thread CTA
    crf_forward_kernel<<<blocks, 64>>>(em, tr, (float*)d_out, B, T);
}